// round 7
// baseline (speedup 1.0000x reference)
#include <cuda_runtime.h>
#include <cuda_bf16.h>
#include <cstdint>
#include <cstddef>

#define NNODE 8192
#define IN_DIM 128
#define HID 512
#define OUTD 256
#define H3 1536
#define O3 768
#define BN_EPS 1e-5f

// ---------------------------------------------------------------------------
// Device scratch (allocation-free). All GEMM operands live in PCS layout:
//   [R,K] bf16 -> 8KB blocks: block(p = r>>7, c = k>>5) at ((p*(K/32)+c)<<13),
//   within-block: sw_off(r&127, (k&31)>>3) + (k&7)*2  (XOR-swizzled 128x32)
// ---------------------------------------------------------------------------
__device__ __align__(1024) __nv_bfloat16 g_adj_h[(size_t)NNODE * NNODE];
__device__ __align__(1024) __nv_bfloat16 g_adj_l[(size_t)NNODE * NNODE];
__device__ __align__(1024) __nv_bfloat16 g_x_h[(size_t)NNODE * IN_DIM];
__device__ __align__(1024) __nv_bfloat16 g_x_l[(size_t)NNODE * IN_DIM];
__device__ __align__(1024) __nv_bfloat16 g_W1t_h[3 * HID * IN_DIM];      // [1536,128]
__device__ __align__(1024) __nv_bfloat16 g_W1t_l[3 * HID * IN_DIM];
__device__ __align__(1024) __nv_bfloat16 g_W2t_h[3 * OUTD * H3];         // [768,1536]
__device__ __align__(1024) __nv_bfloat16 g_W2t_l[3 * OUTD * H3];
__device__ __align__(1024) __nv_bfloat16 g_Wft_h[OUTD * O3];             // [256,768]
__device__ __align__(1024) __nv_bfloat16 g_Wft_l[OUTD * O3];
__device__ __align__(1024) __nv_bfloat16 g_T12t_h[(size_t)2 * HID * NNODE]; // [1024,8192]
__device__ __align__(1024) __nv_bfloat16 g_T12t_l[(size_t)2 * HID * NNODE];
__device__ __align__(1024) __nv_bfloat16 g_T3t_h[(size_t)HID * NNODE];      // [512,8192]
__device__ __align__(1024) __nv_bfloat16 g_T3t_l[(size_t)HID * NNODE];
__device__ __align__(1024) __nv_bfloat16 g_U12t_h[(size_t)HID * NNODE];     // [512,8192]
__device__ __align__(1024) __nv_bfloat16 g_U12t_l[(size_t)HID * NNODE];
__device__ __align__(1024) __nv_bfloat16 g_U3t_h[(size_t)OUTD * NNODE];     // [256,8192]
__device__ __align__(1024) __nv_bfloat16 g_U3t_l[(size_t)OUTD * NNODE];
__device__ float g_h1[(size_t)NNODE * H3];                                  // row-major fp32
__device__ __align__(1024) __nv_bfloat16 g_h1_h[(size_t)NNODE * H3];        // PCS [8192,1536]
__device__ __align__(1024) __nv_bfloat16 g_h1_l[(size_t)NNODE * H3];
__device__ __align__(1024) __nv_bfloat16 g_h2_h[(size_t)NNODE * O3];        // PCS [8192,768]
__device__ __align__(1024) __nv_bfloat16 g_h2_l[(size_t)NNODE * O3];
__device__ double g_sum[H3];
__device__ double g_sq[H3];

// ---------------------------------------------------------------------------
// PTX helpers (all sm_90-baseline: compile at compute_100)
// ---------------------------------------------------------------------------
__device__ __forceinline__ uint32_t smem_u32(const void* p) {
    uint32_t a;
    asm("{ .reg .u64 t; cvta.to.shared.u64 t, %1; cvt.u32.u64 %0, t; }"
        : "=r"(a) : "l"(p));
    return a;
}

__device__ __forceinline__ void ldm_x4(uint32_t* r, uint32_t a) {
    asm volatile("ldmatrix.sync.aligned.m8n8.x4.shared.b16 {%0,%1,%2,%3}, [%4];"
        : "=r"(r[0]), "=r"(r[1]), "=r"(r[2]), "=r"(r[3]) : "r"(a));
}

__device__ __forceinline__ void mma_bf16(float* c, const uint32_t* a, const uint32_t* b) {
    asm volatile(
        "mma.sync.aligned.m16n8k16.row.col.f32.bf16.bf16.f32 "
        "{%0,%1,%2,%3}, {%4,%5,%6,%7}, {%8,%9}, {%0,%1,%2,%3};"
        : "+f"(c[0]), "+f"(c[1]), "+f"(c[2]), "+f"(c[3])
        : "r"(a[0]), "r"(a[1]), "r"(a[2]), "r"(a[3]), "r"(b[0]), "r"(b[1]));
}

// swizzled offset within an 8KB 128x32 bf16 block; c = 16B-chunk index 0..3
__device__ __forceinline__ uint32_t sw_off(int r, int c) {
    return (uint32_t)(r * 64 + ((c ^ ((r >> 1) & 3)) << 4));
}

// byte offset of element (r,k) in a PCS bf16 matrix with K columns
__device__ __forceinline__ size_t pcs_off(int r, int k, int K) {
    const size_t blk = ((size_t)(r >> 7) * (size_t)(K >> 5) + (size_t)(k >> 5)) << 13;
    return blk + sw_off(r & 127, (k & 31) >> 3) + (size_t)((k & 7) * 2);
}

#define MBAR_INIT(a, n) \
    asm volatile("mbarrier.init.shared.b64 [%0], %1;" :: "r"(a), "r"((uint32_t)(n)) : "memory")
#define MBAR_EXPECT(a, n) \
    asm volatile("mbarrier.arrive.expect_tx.shared.b64 _, [%0], %1;" \
                 :: "r"(a), "r"((uint32_t)(n)) : "memory")
#define MBAR_ARRIVE(a) \
    asm volatile("mbarrier.arrive.shared.b64 _, [%0];" :: "r"(a) : "memory")

#define MBAR_WAIT(a, ph) do {                                                     \
    uint32_t _m = (a); uint32_t _p = (uint32_t)(ph); uint32_t _d;                 \
    asm volatile(                                                                 \
        "{\n\t.reg .pred p;\n\t"                                                  \
        "mbarrier.try_wait.parity.acquire.cta.shared::cta.b64 p, [%1], %2;\n\t"   \
        "selp.b32 %0, 1, 0, p;\n\t}"                                              \
        : "=r"(_d) : "r"(_m), "r"(_p) : "memory");                                \
    if (!_d) {                                                                    \
        asm volatile(                                                             \
            "{\n\t.reg .pred P1;\n\t"                                             \
            "WL_%=:\n\t"                                                          \
            "mbarrier.try_wait.parity.acquire.cta.shared::cta.b64 P1, [%0], %1, 0x989680;\n\t" \
            "@P1 bra.uni WD_%=;\n\t"                                              \
            "bra.uni WL_%=;\n\t"                                                  \
            "WD_%=:\n\t}"                                                         \
            :: "r"(_m), "r"(_p) : "memory");                                      \
    }                                                                             \
} while (0)

// 8KB bulk copy global -> shared with mbarrier transaction tracking
__device__ __forceinline__ void bulk_g2s(uint32_t dst, const void* src, uint32_t mbar) {
    asm volatile(
        "cp.async.bulk.shared::cluster.global.mbarrier::complete_tx::bytes [%0], [%1], %2, [%3];"
        :: "r"(dst), "l"(src), "r"(8192u), "r"(mbar) : "memory");
}

// ---------------------------------------------------------------------------
// Split-precision bf16 GEMM via mma.sync, producer-warp bulk loader:
//   C[M,N] = A[M,K] @ B^T    (A: PCS [M,K]; B: PCS [N,K])
//   D += Ah*Bh + Ah*Bl + Al*Bh  (fp32 accum)
// 288 threads: warp 0 = producer (cp.async.bulk, paced by free[] mbarriers,
//   arrive-count 8 = one LANE-0 arrive per consumer warp per pass);
// warps 1..8 = consumers (2x4 layout, warp tile 64x(BN/4)).
// 4-stage ring, full[]/free[] mbarrier pairs, chunks processed in PAIRS
// (KC even for all call sites). No __syncthreads in the mainloop.
// Epilogue (global col gc):
//   gc < splitcol:  Cf != null -> fp32 row-major C (+bias)
//                   else       -> PCS bf16 hi/lo (Ch, Cl), K=ldc, col gc+colofs
//   gc >= splitcol: transposed PCS bf16 hi/lo T at (gc-splitcol, row), K=NNODE
// ---------------------------------------------------------------------------
template <int BN>
__global__ void __launch_bounds__(288, 1)
gemm_mma(const __nv_bfloat16* __restrict__ Ah, const __nv_bfloat16* __restrict__ Al,
         const __nv_bfloat16* __restrict__ Bh, const __nv_bfloat16* __restrict__ Bl,
         int K,
         float* __restrict__ Cf,
         __nv_bfloat16* __restrict__ Ch, __nv_bfloat16* __restrict__ Cl,
         int ldc, int colofs,
         __nv_bfloat16* __restrict__ Th, __nv_bfloat16* __restrict__ Tl,
         int splitcol, const float* __restrict__ bias)
{
    constexpr int WN = BN / 4;            // warp tile cols
    constexpr int NT = WN / 8;
    constexpr int NP = WN / 16;
    constexpr int NPAN = BN / 128;        // B panels per CTA tile
    constexpr int AS = 8192;              // A half-tile bytes
    constexpr int OBH = 2 * AS;
    constexpr int OBL = 2 * AS + NPAN * 8192;
    constexpr int STG = (2 + 2 * NPAN) * 8192;
    extern __shared__ char smem[];
    const uint32_t sb = smem_u32(smem);
    const uint32_t fullb = sb;            // 4 x 8B
    const uint32_t freeb = sb + 32;       // 4 x 8B
    const uint32_t db = sb + 1024;

    const int tid = threadIdx.x;
    const int bx = blockIdx.x, by = blockIdx.y;
    const int KC = K >> 5;                // even for all call sites

    if (tid == 0) {
        #pragma unroll
        for (int b = 0; b < 4; b++) {
            MBAR_INIT(fullb + 8 * b, 1);
            MBAR_INIT(freeb + 8 * b, 8);   // one arrive per consumer warp
        }
    }
    __syncthreads();

    // ================= producer warp =================
    if (tid < 32) {
        if (tid == 0) {
            for (int c = 0; c < KC; c += 2) {
                if (c >= 4) {
                    const uint32_t pp = (uint32_t)(((c >> 2) - 1) & 1);
                    MBAR_WAIT(freeb + 8 * (c & 3), pp);
                    MBAR_WAIT(freeb + 8 * ((c + 1) & 3), pp);
                }
                #pragma unroll
                for (int q = 0; q < 2; q++) {
                    const int cc = c + q;
                    const int b = cc & 3;
                    const uint32_t mb = fullb + 8 * b;
                    const uint32_t dst = db + (uint32_t)b * STG;
                    MBAR_EXPECT(mb, STG);
                    bulk_g2s(dst,      (const char*)Ah + (((size_t)by * KC + cc) << 13), mb);
                    bulk_g2s(dst + AS, (const char*)Al + (((size_t)by * KC + cc) << 13), mb);
                    #pragma unroll
                    for (int p = 0; p < NPAN; p++) {
                        const size_t bo = ((size_t)(bx * NPAN + p) * KC + cc) << 13;
                        bulk_g2s(dst + OBH + p * 8192, (const char*)Bh + bo, mb);
                        bulk_g2s(dst + OBL + p * 8192, (const char*)Bl + bo, mb);
                    }
                }
            }
        }
        return;
    }

    // ================= consumer warps =================
    const int w = (tid >> 5) - 1;         // 0..7
    const int l = tid & 31;
    const int RM = (w >> 2) * 64;
    const int CN = (w & 3) * WN;

    uint32_t aoff[4][2];
    #pragma unroll
    for (int mt = 0; mt < 4; mt++) {
        const int r = RM + mt * 16 + (l & 15);
        #pragma unroll
        for (int ks = 0; ks < 2; ks++)
            aoff[mt][ks] = sw_off(r, ks * 2 + (l >> 4));
    }
    uint32_t boff[NP][2];
    #pragma unroll
    for (int np = 0; np < NP; np++) {
        const int r = CN + np * 16 + ((l >> 4) << 3) + (l & 7);
        #pragma unroll
        for (int ks = 0; ks < 2; ks++)
            boff[np][ks] = sw_off(r, ks * 2 + ((l >> 3) & 1));
    }

    float acc[4][NT][4];
    #pragma unroll
    for (int mt = 0; mt < 4; mt++)
        #pragma unroll
        for (int nt = 0; nt < NT; nt++)
            #pragma unroll
            for (int k = 0; k < 4; k++) acc[mt][nt][k] = 0.0f;

    for (int c = 0; c < KC; c += 2) {
        const uint32_t ph = (uint32_t)((c >> 2) & 1);
        MBAR_WAIT(fullb + 8 * (c & 3), ph);
        MBAR_WAIT(fullb + 8 * ((c + 1) & 3), ph);

        #pragma unroll
        for (int q = 0; q < 2; q++) {
            const uint32_t sbase = db + (uint32_t)((c + q) & 3) * STG;
            #pragma unroll
            for (int ks = 0; ks < 2; ks++) {
                uint32_t ahf[4][4], alf[4][4];
                #pragma unroll
                for (int mt = 0; mt < 4; mt++) {
                    ldm_x4(ahf[mt], sbase + aoff[mt][ks]);
                    ldm_x4(alf[mt], sbase + AS + aoff[mt][ks]);
                }
                #pragma unroll
                for (int np = 0; np < NP; np++) {
                    uint32_t bh[4], bl[4];
                    ldm_x4(bh, sbase + OBH + boff[np][ks]);
                    ldm_x4(bl, sbase + OBL + boff[np][ks]);
                    #pragma unroll
                    for (int mt = 0; mt < 4; mt++)
                        #pragma unroll
                        for (int s = 0; s < 2; s++) {
                            float* a = acc[mt][2 * np + s];
                            mma_bf16(a, ahf[mt], &bh[s * 2]);
                            mma_bf16(a, ahf[mt], &bl[s * 2]);
                            mma_bf16(a, alf[mt], &bh[s * 2]);
                        }
                }
            }
        }
        // warp-synchronous mma/ldmatrix above: when lane 0 gets here, the whole
        // warp is done reading these buffers. ONE arrive per warp (count 8).
        if (l == 0) {
            MBAR_ARRIVE(freeb + 8 * (c & 3));
            MBAR_ARRIVE(freeb + 8 * ((c + 1) & 3));
        }
    }

    // ---- epilogue ----
    #pragma unroll
    for (int mt = 0; mt < 4; mt++) {
        const int r0 = by * 128 + RM + mt * 16 + (l >> 2);
        #pragma unroll
        for (int nt = 0; nt < NT; nt++) {
            const int gc = bx * BN + CN + nt * 8 + ((l & 3) << 1);
            float v0 = acc[mt][nt][0], v1 = acc[mt][nt][1];
            float v2 = acc[mt][nt][2], v3 = acc[mt][nt][3];
            if (bias) {
                const float bb0 = __ldg(bias + gc), bb1 = __ldg(bias + gc + 1);
                v0 += bb0; v1 += bb1; v2 += bb0; v3 += bb1;
            }
            if (gc < splitcol) {
                if (Cf) {
                    *(float2*)&Cf[(size_t)r0 * ldc + gc] = make_float2(v0, v1);
                    *(float2*)&Cf[(size_t)(r0 + 8) * ldc + gc] = make_float2(v2, v3);
                } else {
                    const int pc = gc + colofs;
                    const __nv_bfloat16 h0 = __float2bfloat16(v0);
                    const __nv_bfloat16 h1 = __float2bfloat16(v1);
                    const __nv_bfloat16 h2 = __float2bfloat16(v2);
                    const __nv_bfloat16 h3 = __float2bfloat16(v3);
                    const size_t oA = pcs_off(r0, pc, ldc);
                    const size_t oB = pcs_off(r0 + 8, pc, ldc);
                    *(__nv_bfloat162*)((char*)Ch + oA) = __halves2bfloat162(h0, h1);
                    *(__nv_bfloat162*)((char*)Ch + oB) = __halves2bfloat162(h2, h3);
                    *(__nv_bfloat162*)((char*)Cl + oA) = __halves2bfloat162(
                        __float2bfloat16(v0 - __bfloat162float(h0)),
                        __float2bfloat16(v1 - __bfloat162float(h1)));
                    *(__nv_bfloat162*)((char*)Cl + oB) = __halves2bfloat162(
                        __float2bfloat16(v2 - __bfloat162float(h2)),
                        __float2bfloat16(v3 - __bfloat162float(h3)));
                }
            } else {
                const int tr = gc - splitcol;
                const float vv[4] = {v0, v1, v2, v3};
                const size_t oo[4] = {
                    pcs_off(tr, r0, NNODE), pcs_off(tr + 1, r0, NNODE),
                    pcs_off(tr, r0 + 8, NNODE), pcs_off(tr + 1, r0 + 8, NNODE)};
                #pragma unroll
                for (int q = 0; q < 4; q++) {
                    const __nv_bfloat16 h = __float2bfloat16(vv[q]);
                    *(__nv_bfloat16*)((char*)Th + oo[q]) = h;
                    *(__nv_bfloat16*)((char*)Tl + oo[q]) =
                        __float2bfloat16(vv[q] - __bfloat162float(h));
                }
            }
        }
    }
}

// ---------------------------------------------------------------------------
// fp32 row-major [R,K] -> PCS bf16 hi/lo
// ---------------------------------------------------------------------------
__global__ void cvt_split_pcs(const float* __restrict__ s,
                              __nv_bfloat16* __restrict__ dh,
                              __nv_bfloat16* __restrict__ dl, int R, int K)
{
    const int K8 = K >> 3;
    const size_t i8 = (size_t)blockIdx.x * 256 + threadIdx.x;
    if (i8 >= (size_t)R * K8) return;
    const int r = (int)(i8 / K8);
    const int k = (int)(i8 % K8) << 3;
    const float4 u0 = *(const float4*)(s + (size_t)r * K + k);
    const float4 u1 = *(const float4*)(s + (size_t)r * K + k + 4);
    const float a[8] = {u0.x, u0.y, u0.z, u0.w, u1.x, u1.y, u1.z, u1.w};
    __nv_bfloat16 hh[8], ll[8];
    #pragma unroll
    for (int q = 0; q < 8; q++) {
        hh[q] = __float2bfloat16(a[q]);
        ll[q] = __float2bfloat16(a[q] - __bfloat162float(hh[q]));
    }
    const size_t o = pcs_off(r, k, K);
    __nv_bfloat162* ph = (__nv_bfloat162*)((char*)dh + o);
    __nv_bfloat162* pl = (__nv_bfloat162*)((char*)dl + o);
    #pragma unroll
    for (int q = 0; q < 4; q++) {
        ph[q] = __halves2bfloat162(hh[2 * q], hh[2 * q + 1]);
        pl[q] = __halves2bfloat162(ll[2 * q], ll[2 * q + 1]);
    }
}

// fp32 [R,C] row-major -> transposed PCS bf16 hi/lo [C rows, R cols]
__global__ void cvt_split_tr_pcs(const float* __restrict__ s,
                                 __nv_bfloat16* __restrict__ dh,
                                 __nv_bfloat16* __restrict__ dl, int R, int C)
{
    __shared__ float t[32][33];
    const int c0 = blockIdx.x * 32, r0 = blockIdx.y * 32;
    const int tx = threadIdx.x, ty = threadIdx.y;
    #pragma unroll
    for (int j = 0; j < 4; j++)
        t[ty + 8 * j][tx] = s[(size_t)(r0 + ty + 8 * j) * C + c0 + tx];
    __syncthreads();
    #pragma unroll
    for (int j = 0; j < 4; j++) {
        const float v = t[tx][ty + 8 * j];
        const __nv_bfloat16 h = __float2bfloat16(v);
        const __nv_bfloat16 l = __float2bfloat16(v - __bfloat162float(h));
        const size_t o = pcs_off(c0 + ty + 8 * j, r0 + tx, R);
        *(__nv_bfloat16*)((char*)dh + o) = h;
        *(__nv_bfloat16*)((char*)dl + o) = l;
    }
}

// ---------------------------------------------------------------------------
// BatchNorm (training stats) + ReLU; fp32 h1 -> PCS bf16 hi/lo
// ---------------------------------------------------------------------------
__global__ void zero_stats()
{
    const int i = blockIdx.x * blockDim.x + threadIdx.x;
    if (i < H3) { g_sum[i] = 0.0; g_sq[i] = 0.0; }
}

__global__ void bn_stats(const float* __restrict__ h)
{
    const int col = blockIdx.x * 256 + threadIdx.x;
    const int r0 = blockIdx.y * 256;
    double ls = 0.0, lq = 0.0;
    #pragma unroll 4
    for (int r = r0; r < r0 + 256; r++) {
        const float v = h[(size_t)r * H3 + col];
        ls += (double)v;
        lq += (double)v * (double)v;
    }
    atomicAdd(&g_sum[col], ls);
    atomicAdd(&g_sq[col], lq);
}

__global__ void bn_apply_pcs(const float* __restrict__ h,
                             const float* __restrict__ gamma,
                             const float* __restrict__ beta,
                             __nv_bfloat16* __restrict__ oh,
                             __nv_bfloat16* __restrict__ ol)
{
    constexpr int K8 = H3 >> 3;
    const size_t i8 = (size_t)blockIdx.x * 256 + threadIdx.x;
    if (i8 >= (size_t)NNODE * K8) return;
    const int r = (int)(i8 / K8);
    const int k = (int)(i8 % K8) << 3;
    const float4 u0 = *(const float4*)(h + (size_t)r * H3 + k);
    const float4 u1 = *(const float4*)(h + (size_t)r * H3 + k + 4);
    const float a[8] = {u0.x, u0.y, u0.z, u0.w, u1.x, u1.y, u1.z, u1.w};
    __nv_bfloat16 hh[8], ll[8];
    #pragma unroll
    for (int q = 0; q < 8; q++) {
        const int col = k + q;
        const double mu = g_sum[col] / (double)NNODE;
        const double var = g_sq[col] / (double)NNODE - mu * mu;
        const float rstd = rsqrtf((float)var + BN_EPS);
        float v = (a[q] - (float)mu) * rstd * gamma[col] + beta[col];
        v = v > 0.0f ? v : 0.0f;
        hh[q] = __float2bfloat16(v);
        ll[q] = __float2bfloat16(v - __bfloat162float(hh[q]));
    }
    const size_t o = pcs_off(r, k, H3);
    __nv_bfloat162* ph = (__nv_bfloat162*)((char*)oh + o);
    __nv_bfloat162* pl = (__nv_bfloat162*)((char*)ol + o);
    #pragma unroll
    for (int q = 0; q < 4; q++) {
        ph[q] = __halves2bfloat162(hh[2 * q], hh[2 * q + 1]);
        pl[q] = __halves2bfloat162(ll[2 * q], ll[2 * q + 1]);
    }
}

// ---------------------------------------------------------------------------
// Orchestration
// ---------------------------------------------------------------------------
extern "C" void kernel_launch(void* const* d_in, const int* in_sizes, int n_in,
                              void* d_out, int out_size)
{
    const float* x     = (const float*)d_in[0];
    const float* adj   = (const float*)d_in[1];
    const float* W1    = (const float*)d_in[2];
    const float* b1    = (const float*)d_in[3];
    const float* W2    = (const float*)d_in[4];
    const float* b2    = (const float*)d_in[5];
    const float* gamma = (const float*)d_in[6];
    const float* beta  = (const float*)d_in[7];
    const float* Wf    = (const float*)d_in[8];
    const float* bf    = (const float*)d_in[9];
    float* out = (float*)d_out;

    __nv_bfloat16 *adj_h, *adj_l, *x_h, *x_l, *W1t_h, *W1t_l, *W2t_h, *W2t_l;
    __nv_bfloat16 *Wft_h, *Wft_l, *T12t_h, *T12t_l, *T3t_h, *T3t_l;
    __nv_bfloat16 *U12t_h, *U12t_l, *U3t_h, *U3t_l, *h1_h, *h1_l, *h2_h, *h2_l;
    float *h1;
    cudaGetSymbolAddress((void**)&adj_h, g_adj_h);
    cudaGetSymbolAddress((void**)&adj_l, g_adj_l);
    cudaGetSymbolAddress((void**)&x_h, g_x_h);
    cudaGetSymbolAddress((void**)&x_l, g_x_l);
    cudaGetSymbolAddress((void**)&W1t_h, g_W1t_h);
    cudaGetSymbolAddress((void**)&W1t_l, g_W1t_l);
    cudaGetSymbolAddress((void**)&W2t_h, g_W2t_h);
    cudaGetSymbolAddress((void**)&W2t_l, g_W2t_l);
    cudaGetSymbolAddress((void**)&Wft_h, g_Wft_h);
    cudaGetSymbolAddress((void**)&Wft_l, g_Wft_l);
    cudaGetSymbolAddress((void**)&T12t_h, g_T12t_h);
    cudaGetSymbolAddress((void**)&T12t_l, g_T12t_l);
    cudaGetSymbolAddress((void**)&T3t_h, g_T3t_h);
    cudaGetSymbolAddress((void**)&T3t_l, g_T3t_l);
    cudaGetSymbolAddress((void**)&U12t_h, g_U12t_h);
    cudaGetSymbolAddress((void**)&U12t_l, g_U12t_l);
    cudaGetSymbolAddress((void**)&U3t_h, g_U3t_h);
    cudaGetSymbolAddress((void**)&U3t_l, g_U3t_l);
    cudaGetSymbolAddress((void**)&h1_h, g_h1_h);
    cudaGetSymbolAddress((void**)&h1_l, g_h1_l);
    cudaGetSymbolAddress((void**)&h2_h, g_h2_h);
    cudaGetSymbolAddress((void**)&h2_l, g_h2_l);
    cudaGetSymbolAddress((void**)&h1, g_h1);

    constexpr int SMEM256 = 1024 + 4 * ((2 + 4) * 8192);  // 197632
    constexpr int SMEM128 = 1024 + 4 * ((2 + 2) * 8192);  // 132096
    cudaFuncSetAttribute(gemm_mma<256>, cudaFuncAttributeMaxDynamicSharedMemorySize, SMEM256);
    cudaFuncSetAttribute(gemm_mma<128>, cudaFuncAttributeMaxDynamicSharedMemorySize, SMEM128);

    const int NOSPLIT = 1 << 30;
    const dim3 blk(288);
    const int MB = NNODE / 128;   // 64

    // ---- input conversions (all into PCS) ----
    {
        const size_t n8x = (size_t)NNODE * IN_DIM / 8;
        cvt_split_pcs<<<(unsigned)((n8x + 255) / 256), 256>>>(x, x_h, x_l, NNODE, IN_DIM);
        const size_t n8a = (size_t)NNODE * NNODE / 8;
        cvt_split_pcs<<<(unsigned)((n8a + 255) / 256), 256>>>(adj, adj_h, adj_l, NNODE, NNODE);
    }
    for (int j = 0; j < 3; j++) {
        cvt_split_tr_pcs<<<dim3(HID / 32, IN_DIM / 32), dim3(32, 8)>>>(
            W1 + (size_t)j * IN_DIM * HID, W1t_h + (size_t)j * HID * IN_DIM,
            W1t_l + (size_t)j * HID * IN_DIM, IN_DIM, HID);
        cvt_split_tr_pcs<<<dim3(OUTD / 32, H3 / 32), dim3(32, 8)>>>(
            W2 + (size_t)j * H3 * OUTD, W2t_h + (size_t)j * OUTD * H3,
            W2t_l + (size_t)j * OUTD * H3, H3, OUTD);
    }
    cvt_split_tr_pcs<<<dim3(OUTD / 32, O3 / 32), dim3(32, 8)>>>(Wf, Wft_h, Wft_l, O3, OUTD);

    // ---- GEMM 1: x @ [W1_0|W1_1|W1_2]  (N=1536; <512 -> h1 fp32, >=512 -> T12^T) ----
    gemm_mma<256><<<dim3(6, MB), blk, SMEM256>>>(x_h, x_l, W1t_h, W1t_l, IN_DIM,
        h1, nullptr, nullptr, H3, 0, T12t_h, T12t_l, 512, b1);

    // ---- GEMM 2: adj @ [T1|T2]  (N=1024; <512 -> h1 hop1 fp32, >=512 -> T3^T) ----
    gemm_mma<256><<<dim3(4, MB), blk, SMEM256>>>(adj_h, adj_l, T12t_h, T12t_l, NNODE,
        h1 + HID, nullptr, nullptr, H3, 0, T3t_h, T3t_l, 512, nullptr);

    // ---- GEMM 3: adj @ T3  (N=512 -> h1 hop2 fp32) ----
    gemm_mma<256><<<dim3(2, MB), blk, SMEM256>>>(adj_h, adj_l, T3t_h, T3t_l, NNODE,
        h1 + 2 * HID, nullptr, nullptr, H3, 0, nullptr, nullptr, NOSPLIT, nullptr);

    // ---- BN + ReLU -> h1 PCS bf16 ----
    zero_stats<<<(H3 + 255) / 256, 256>>>();
    bn_stats<<<dim3(H3 / 256, NNODE / 256), 256>>>(h1);
    {
        const size_t n8 = (size_t)NNODE * H3 / 8;
        bn_apply_pcs<<<(unsigned)((n8 + 255) / 256), 256>>>(h1, gamma, beta, h1_h, h1_l);
    }

    // ---- GEMM 4: h1 @ [W2_0|W2_1|W2_2]  (N=768; <256 -> h2 PCS cols 0-255, >=256 -> U12^T) ----
    gemm_mma<256><<<dim3(3, MB), blk, SMEM256>>>(h1_h, h1_l, W2t_h, W2t_l, H3,
        nullptr, h2_h, h2_l, O3, 0, U12t_h, U12t_l, 256, b2);

    // ---- GEMM 5: adj @ [U1|U2]  (N=512; <256 -> h2 PCS cols 256-511, >=256 -> U3^T) ----
    gemm_mma<256><<<dim3(2, MB), blk, SMEM256>>>(adj_h, adj_l, U12t_h, U12t_l, NNODE,
        nullptr, h2_h, h2_l, O3, OUTD, U3t_h, U3t_l, 256, nullptr);

    // ---- GEMM 6: adj @ U3  (N=256 -> h2 PCS cols 512-767) ----
    gemm_mma<128><<<dim3(2, MB), blk, SMEM128>>>(adj_h, adj_l, U3t_h, U3t_l, NNODE,
        nullptr, h2_h, h2_l, O3, 2 * OUTD, nullptr, nullptr, NOSPLIT, nullptr);

    // ---- GEMM 7: out = h2 @ Wf + bf  (N=256, fp32) ----
    gemm_mma<128><<<dim3(2, MB), blk, SMEM128>>>(h2_h, h2_l, Wft_h, Wft_l, O3,
        out, nullptr, nullptr, OUTD, 0, nullptr, nullptr, NOSPLIT, bf);
}

// round 9
// speedup vs baseline: 1.0587x; 1.0587x over previous
#include <cuda_runtime.h>
#include <cuda_bf16.h>
#include <cstdint>
#include <cstddef>

#define NNODE 8192
#define IN_DIM 128
#define HID 512
#define OUTD 256
#define H3 1536
#define O3 768
#define BN_EPS 1e-5f

// ---------------------------------------------------------------------------
// Device scratch (allocation-free). All GEMM operands live in PCS layout:
//   [R,K] bf16 -> 8KB blocks: block(p = r>>7, c = k>>5) at ((p*(K/32)+c)<<13),
//   within-block: sw_off(r&127, (k&31)>>3) + (k&7)*2  (XOR-swizzled 128x32)
// ---------------------------------------------------------------------------
__device__ __align__(1024) __nv_bfloat16 g_adj_h[(size_t)NNODE * NNODE];
__device__ __align__(1024) __nv_bfloat16 g_adj_l[(size_t)NNODE * NNODE];
__device__ __align__(1024) __nv_bfloat16 g_x_h[(size_t)NNODE * IN_DIM];
__device__ __align__(1024) __nv_bfloat16 g_x_l[(size_t)NNODE * IN_DIM];
__device__ __align__(1024) __nv_bfloat16 g_W1t_h[3 * HID * IN_DIM];      // [1536,128]
__device__ __align__(1024) __nv_bfloat16 g_W1t_l[3 * HID * IN_DIM];
__device__ __align__(1024) __nv_bfloat16 g_W2t_h[3 * OUTD * H3];         // [768,1536]
__device__ __align__(1024) __nv_bfloat16 g_W2t_l[3 * OUTD * H3];
__device__ __align__(1024) __nv_bfloat16 g_Wft_h[OUTD * O3];             // [256,768]
__device__ __align__(1024) __nv_bfloat16 g_Wft_l[OUTD * O3];
__device__ __align__(1024) __nv_bfloat16 g_T12t_h[(size_t)2 * HID * NNODE]; // [1024,8192]
__device__ __align__(1024) __nv_bfloat16 g_T12t_l[(size_t)2 * HID * NNODE];
__device__ __align__(1024) __nv_bfloat16 g_T3t_h[(size_t)HID * NNODE];      // [512,8192]
__device__ __align__(1024) __nv_bfloat16 g_T3t_l[(size_t)HID * NNODE];
__device__ __align__(1024) __nv_bfloat16 g_U12t_h[(size_t)HID * NNODE];     // [512,8192]
__device__ __align__(1024) __nv_bfloat16 g_U12t_l[(size_t)HID * NNODE];
__device__ __align__(1024) __nv_bfloat16 g_U3t_h[(size_t)OUTD * NNODE];     // [256,8192]
__device__ __align__(1024) __nv_bfloat16 g_U3t_l[(size_t)OUTD * NNODE];
__device__ float g_h1[(size_t)NNODE * H3];                                  // row-major fp32
__device__ __align__(1024) __nv_bfloat16 g_h1_h[(size_t)NNODE * H3];        // PCS [8192,1536]
__device__ __align__(1024) __nv_bfloat16 g_h1_l[(size_t)NNODE * H3];
__device__ __align__(1024) __nv_bfloat16 g_h2_h[(size_t)NNODE * O3];        // PCS [8192,768]
__device__ __align__(1024) __nv_bfloat16 g_h2_l[(size_t)NNODE * O3];
__device__ double g_sum[H3];
__device__ double g_sq[H3];

// ---------------------------------------------------------------------------
// PTX helpers (all sm_90-baseline: compile at compute_100)
// ---------------------------------------------------------------------------
__device__ __forceinline__ uint32_t smem_u32(const void* p) {
    uint32_t a;
    asm("{ .reg .u64 t; cvta.to.shared.u64 t, %1; cvt.u32.u64 %0, t; }"
        : "=r"(a) : "l"(p));
    return a;
}

__device__ __forceinline__ void ldm_x4(uint32_t* r, uint32_t a) {
    asm volatile("ldmatrix.sync.aligned.m8n8.x4.shared.b16 {%0,%1,%2,%3}, [%4];"
        : "=r"(r[0]), "=r"(r[1]), "=r"(r[2]), "=r"(r[3]) : "r"(a));
}

__device__ __forceinline__ void mma_bf16(float* c, const uint32_t* a, const uint32_t* b) {
    asm volatile(
        "mma.sync.aligned.m16n8k16.row.col.f32.bf16.bf16.f32 "
        "{%0,%1,%2,%3}, {%4,%5,%6,%7}, {%8,%9}, {%0,%1,%2,%3};"
        : "+f"(c[0]), "+f"(c[1]), "+f"(c[2]), "+f"(c[3])
        : "r"(a[0]), "r"(a[1]), "r"(a[2]), "r"(a[3]), "r"(b[0]), "r"(b[1]));
}

// swizzled offset within an 8KB 128x32 bf16 block; c = 16B-chunk index 0..3
__device__ __forceinline__ uint32_t sw_off(int r, int c) {
    return (uint32_t)(r * 64 + ((c ^ ((r >> 1) & 3)) << 4));
}

// byte offset of element (r,k) in a PCS bf16 matrix with K columns
__device__ __forceinline__ size_t pcs_off(int r, int k, int K) {
    const size_t blk = ((size_t)(r >> 7) * (size_t)(K >> 5) + (size_t)(k >> 5)) << 13;
    return blk + sw_off(r & 127, (k & 31) >> 3) + (size_t)((k & 7) * 2);
}

#define MBAR_INIT(a, n) \
    asm volatile("mbarrier.init.shared.b64 [%0], %1;" :: "r"(a), "r"((uint32_t)(n)) : "memory")
#define MBAR_EXPECT(a, n) \
    asm volatile("mbarrier.arrive.expect_tx.shared.b64 _, [%0], %1;" \
                 :: "r"(a), "r"((uint32_t)(n)) : "memory")

#define MBAR_WAIT(a, ph) do {                                                     \
    uint32_t _m = (a); uint32_t _p = (uint32_t)(ph); uint32_t _d;                 \
    asm volatile(                                                                 \
        "{\n\t.reg .pred p;\n\t"                                                  \
        "mbarrier.try_wait.parity.acquire.cta.shared::cta.b64 p, [%1], %2;\n\t"   \
        "selp.b32 %0, 1, 0, p;\n\t}"                                              \
        : "=r"(_d) : "r"(_m), "r"(_p) : "memory");                                \
    if (!_d) {                                                                    \
        asm volatile(                                                             \
            "{\n\t.reg .pred P1;\n\t"                                             \
            "WL_%=:\n\t"                                                          \
            "mbarrier.try_wait.parity.acquire.cta.shared::cta.b64 P1, [%0], %1, 0x989680;\n\t" \
            "@P1 bra.uni WD_%=;\n\t"                                              \
            "bra.uni WL_%=;\n\t"                                                  \
            "WD_%=:\n\t}"                                                         \
            :: "r"(_m), "r"(_p) : "memory");                                      \
    }                                                                             \
} while (0)

// 8KB bulk copy global -> shared with mbarrier transaction tracking
__device__ __forceinline__ void bulk_g2s(uint32_t dst, const void* src, uint32_t mbar) {
    asm volatile(
        "cp.async.bulk.shared::cluster.global.mbarrier::complete_tx::bytes [%0], [%1], %2, [%3];"
        :: "r"(dst), "l"(src), "r"(8192u), "r"(mbar) : "memory");
}

// ---------------------------------------------------------------------------
// Split-precision bf16 GEMM via mma.sync, bulk-copy loader:
//   C[M,N] = A[M,K] @ B^T    (A: PCS [M,K]; B: PCS [N,K])
//   D += Ah*Bh + Ah*Bl + Al*Bh  (fp32 accum; per-acc order hh,hl,lh preserved)
// CTA tile 128xBNx32, 256 threads (8 warps, 2x4), warp tile 64x(BN/4).
// 4-stage ring; chunks processed in PAIRS (KC % 4 == 0 for all call sites):
// wait both stage barriers, compute pair, ONE __syncthreads, refill pair.
// Epilogue (global col gc):
//   gc < splitcol:  Cf != null -> fp32 row-major C (+bias)
//                   else       -> PCS bf16 hi/lo (Ch, Cl), K=ldc, col gc+colofs
//   gc >= splitcol: transposed PCS bf16 hi/lo T at (gc-splitcol, row), K=NNODE
// ---------------------------------------------------------------------------
template <int BN>
__global__ void __launch_bounds__(256, 1)
gemm_mma(const __nv_bfloat16* __restrict__ Ah, const __nv_bfloat16* __restrict__ Al,
         const __nv_bfloat16* __restrict__ Bh, const __nv_bfloat16* __restrict__ Bl,
         int K,
         float* __restrict__ Cf,
         __nv_bfloat16* __restrict__ Ch, __nv_bfloat16* __restrict__ Cl,
         int ldc, int colofs,
         __nv_bfloat16* __restrict__ Th, __nv_bfloat16* __restrict__ Tl,
         int splitcol, const float* __restrict__ bias)
{
    constexpr int WN = BN / 4;            // warp tile cols
    constexpr int NT = WN / 8;
    constexpr int NP = WN / 16;
    constexpr int NPAN = BN / 128;        // B panels per CTA tile
    constexpr int AS = 8192;              // A half-tile bytes
    constexpr int OBH = 2 * AS;
    constexpr int OBL = 2 * AS + NPAN * 8192;
    constexpr int STG = (2 + 2 * NPAN) * 8192;
    extern __shared__ char smem[];
    const uint32_t sb = smem_u32(smem);
    const uint32_t db = sb + 1024;

    const int tid = threadIdx.x;
    const int bx = blockIdx.x, by = blockIdx.y;
    const int KC = K >> 5;                // multiple of 4 for all call sites

    if (tid == 0) {
        #pragma unroll
        for (int b = 0; b < 4; b++) MBAR_INIT(sb + 8 * b, 1);
    }
    __syncthreads();

    auto issue = [&](int c) {
        const int b = c & 3;
        const uint32_t mb = sb + 8 * b;
        const uint32_t dst = db + (uint32_t)b * STG;
        MBAR_EXPECT(mb, STG);
        bulk_g2s(dst,      (const char*)Ah + (((size_t)by * KC + c) << 13), mb);
        bulk_g2s(dst + AS, (const char*)Al + (((size_t)by * KC + c) << 13), mb);
        #pragma unroll
        for (int p = 0; p < NPAN; p++) {
            const size_t bo = ((size_t)(bx * NPAN + p) * KC + c) << 13;
            bulk_g2s(dst + OBH + p * 8192, (const char*)Bh + bo, mb);
            bulk_g2s(dst + OBL + p * 8192, (const char*)Bl + bo, mb);
        }
    };

    if (tid == 0) {
        issue(0); issue(1); issue(2); issue(3);
    }

    // ---- compute mapping: 8 warps, 2 rows x 4 cols ----
    const int w = tid >> 5, l = tid & 31;
    const int RM = (w >> 2) * 64;
    const int CN = (w & 3) * WN;

    uint32_t aoff[4][2];
    #pragma unroll
    for (int mt = 0; mt < 4; mt++) {
        const int r = RM + mt * 16 + (l & 15);
        #pragma unroll
        for (int ks = 0; ks < 2; ks++)
            aoff[mt][ks] = sw_off(r, ks * 2 + (l >> 4));
    }
    uint32_t boff[NP][2];
    #pragma unroll
    for (int np = 0; np < NP; np++) {
        const int r = CN + np * 16 + ((l >> 4) << 3) + (l & 7);
        #pragma unroll
        for (int ks = 0; ks < 2; ks++)
            boff[np][ks] = sw_off(r, ks * 2 + ((l >> 3) & 1));
    }

    float acc[4][NT][4];
    #pragma unroll
    for (int mt = 0; mt < 4; mt++)
        #pragma unroll
        for (int nt = 0; nt < NT; nt++)
            #pragma unroll
            for (int k = 0; k < 4; k++) acc[mt][nt][k] = 0.0f;

    for (int c = 0; c < KC; c += 2) {
        const uint32_t ph = (uint32_t)((c >> 2) & 1);
        MBAR_WAIT(sb + 8 * (c & 3), ph);
        MBAR_WAIT(sb + 8 * ((c + 1) & 3), ph);

        #pragma unroll
        for (int q = 0; q < 2; q++) {
            const uint32_t sbase = db + (uint32_t)((c + q) & 3) * STG;
            #pragma unroll
            for (int ks = 0; ks < 2; ks++) {
                uint32_t ahf[4][4], alf[4][4], bhf[NP][4], blf[NP][4];
                #pragma unroll
                for (int mt = 0; mt < 4; mt++) {
                    ldm_x4(ahf[mt], sbase + aoff[mt][ks]);
                    ldm_x4(alf[mt], sbase + AS + aoff[mt][ks]);
                }
                #pragma unroll
                for (int np = 0; np < NP; np++) {
                    ldm_x4(bhf[np], sbase + OBH + boff[np][ks]);
                    ldm_x4(blf[np], sbase + OBL + boff[np][ks]);
                }
                // Product-major ordering: each acc touched once per sweep
                // (per-acc order hh -> hl -> lh preserved = identical numerics)
                #pragma unroll
                for (int np = 0; np < NP; np++)
                    #pragma unroll
                    for (int mt = 0; mt < 4; mt++)
                        #pragma unroll
                        for (int s = 0; s < 2; s++)
                            mma_bf16(acc[mt][2 * np + s], ahf[mt], &bhf[np][s * 2]);
                #pragma unroll
                for (int np = 0; np < NP; np++)
                    #pragma unroll
                    for (int mt = 0; mt < 4; mt++)
                        #pragma unroll
                        for (int s = 0; s < 2; s++)
                            mma_bf16(acc[mt][2 * np + s], ahf[mt], &blf[np][s * 2]);
                #pragma unroll
                for (int np = 0; np < NP; np++)
                    #pragma unroll
                    for (int mt = 0; mt < 4; mt++)
                        #pragma unroll
                        for (int s = 0; s < 2; s++)
                            mma_bf16(acc[mt][2 * np + s], alf[mt], &bhf[np][s * 2]);
            }
        }
        __syncthreads();
        if (tid == 0) {
            if (c + 4 < KC) issue(c + 4);
            if (c + 5 < KC) issue(c + 5);
        }
    }

    // ---- epilogue ----
    #pragma unroll
    for (int mt = 0; mt < 4; mt++) {
        const int r0 = by * 128 + RM + mt * 16 + (l >> 2);
        #pragma unroll
        for (int nt = 0; nt < NT; nt++) {
            const int gc = bx * BN + CN + nt * 8 + ((l & 3) << 1);
            float v0 = acc[mt][nt][0], v1 = acc[mt][nt][1];
            float v2 = acc[mt][nt][2], v3 = acc[mt][nt][3];
            if (bias) {
                const float bb0 = __ldg(bias + gc), bb1 = __ldg(bias + gc + 1);
                v0 += bb0; v1 += bb1; v2 += bb0; v3 += bb1;
            }
            if (gc < splitcol) {
                if (Cf) {
                    *(float2*)&Cf[(size_t)r0 * ldc + gc] = make_float2(v0, v1);
                    *(float2*)&Cf[(size_t)(r0 + 8) * ldc + gc] = make_float2(v2, v3);
                } else {
                    const int pc = gc + colofs;
                    const __nv_bfloat16 h0 = __float2bfloat16(v0);
                    const __nv_bfloat16 h1 = __float2bfloat16(v1);
                    const __nv_bfloat16 h2 = __float2bfloat16(v2);
                    const __nv_bfloat16 h3 = __float2bfloat16(v3);
                    const size_t oA = pcs_off(r0, pc, ldc);
                    const size_t oB = pcs_off(r0 + 8, pc, ldc);
                    *(__nv_bfloat162*)((char*)Ch + oA) = __halves2bfloat162(h0, h1);
                    *(__nv_bfloat162*)((char*)Ch + oB) = __halves2bfloat162(h2, h3);
                    *(__nv_bfloat162*)((char*)Cl + oA) = __halves2bfloat162(
                        __float2bfloat16(v0 - __bfloat162float(h0)),
                        __float2bfloat16(v1 - __bfloat162float(h1)));
                    *(__nv_bfloat162*)((char*)Cl + oB) = __halves2bfloat162(
                        __float2bfloat16(v2 - __bfloat162float(h2)),
                        __float2bfloat16(v3 - __bfloat162float(h3)));
                }
            } else {
                const int tr = gc - splitcol;
                const float vv[4] = {v0, v1, v2, v3};
                const size_t oo[4] = {
                    pcs_off(tr, r0, NNODE), pcs_off(tr + 1, r0, NNODE),
                    pcs_off(tr, r0 + 8, NNODE), pcs_off(tr + 1, r0 + 8, NNODE)};
                #pragma unroll
                for (int q = 0; q < 4; q++) {
                    const __nv_bfloat16 h = __float2bfloat16(vv[q]);
                    *(__nv_bfloat16*)((char*)Th + oo[q]) = h;
                    *(__nv_bfloat16*)((char*)Tl + oo[q]) =
                        __float2bfloat16(vv[q] - __bfloat162float(h));
                }
            }
        }
    }
}

// ---------------------------------------------------------------------------
// fp32 row-major [R,K] -> PCS bf16 hi/lo
// ---------------------------------------------------------------------------
__global__ void cvt_split_pcs(const float* __restrict__ s,
                              __nv_bfloat16* __restrict__ dh,
                              __nv_bfloat16* __restrict__ dl, int R, int K)
{
    const int K8 = K >> 3;
    const size_t i8 = (size_t)blockIdx.x * 256 + threadIdx.x;
    if (i8 >= (size_t)R * K8) return;
    const int r = (int)(i8 / K8);
    const int k = (int)(i8 % K8) << 3;
    const float4 u0 = *(const float4*)(s + (size_t)r * K + k);
    const float4 u1 = *(const float4*)(s + (size_t)r * K + k + 4);
    const float a[8] = {u0.x, u0.y, u0.z, u0.w, u1.x, u1.y, u1.z, u1.w};
    __nv_bfloat16 hh[8], ll[8];
    #pragma unroll
    for (int q = 0; q < 8; q++) {
        hh[q] = __float2bfloat16(a[q]);
        ll[q] = __float2bfloat16(a[q] - __bfloat162float(hh[q]));
    }
    const size_t o = pcs_off(r, k, K);
    __nv_bfloat162* ph = (__nv_bfloat162*)((char*)dh + o);
    __nv_bfloat162* pl = (__nv_bfloat162*)((char*)dl + o);
    #pragma unroll
    for (int q = 0; q < 4; q++) {
        ph[q] = __halves2bfloat162(hh[2 * q], hh[2 * q + 1]);
        pl[q] = __halves2bfloat162(ll[2 * q], ll[2 * q + 1]);
    }
}

// fp32 [R,C] row-major -> transposed PCS bf16 hi/lo [C rows, R cols]
__global__ void cvt_split_tr_pcs(const float* __restrict__ s,
                                 __nv_bfloat16* __restrict__ dh,
                                 __nv_bfloat16* __restrict__ dl, int R, int C)
{
    __shared__ float t[32][33];
    const int c0 = blockIdx.x * 32, r0 = blockIdx.y * 32;
    const int tx = threadIdx.x, ty = threadIdx.y;
    #pragma unroll
    for (int j = 0; j < 4; j++)
        t[ty + 8 * j][tx] = s[(size_t)(r0 + ty + 8 * j) * C + c0 + tx];
    __syncthreads();
    #pragma unroll
    for (int j = 0; j < 4; j++) {
        const float v = t[tx][ty + 8 * j];
        const __nv_bfloat16 h = __float2bfloat16(v);
        const __nv_bfloat16 l = __float2bfloat16(v - __bfloat162float(h));
        const size_t o = pcs_off(c0 + ty + 8 * j, r0 + tx, R);
        *(__nv_bfloat16*)((char*)dh + o) = h;
        *(__nv_bfloat16*)((char*)dl + o) = l;
    }
}

// ---------------------------------------------------------------------------
// BatchNorm (training stats) + ReLU; fp32 h1 -> PCS bf16 hi/lo
// ---------------------------------------------------------------------------
__global__ void zero_stats()
{
    const int i = blockIdx.x * blockDim.x + threadIdx.x;
    if (i < H3) { g_sum[i] = 0.0; g_sq[i] = 0.0; }
}

__global__ void bn_stats(const float* __restrict__ h)
{
    const int col = blockIdx.x * 256 + threadIdx.x;
    const int r0 = blockIdx.y * 256;
    double ls = 0.0, lq = 0.0;
    #pragma unroll 4
    for (int r = r0; r < r0 + 256; r++) {
        const float v = h[(size_t)r * H3 + col];
        ls += (double)v;
        lq += (double)v * (double)v;
    }
    atomicAdd(&g_sum[col], ls);
    atomicAdd(&g_sq[col], lq);
}

__global__ void bn_apply_pcs(const float* __restrict__ h,
                             const float* __restrict__ gamma,
                             const float* __restrict__ beta,
                             __nv_bfloat16* __restrict__ oh,
                             __nv_bfloat16* __restrict__ ol)
{
    constexpr int K8 = H3 >> 3;
    const size_t i8 = (size_t)blockIdx.x * 256 + threadIdx.x;
    if (i8 >= (size_t)NNODE * K8) return;
    const int r = (int)(i8 / K8);
    const int k = (int)(i8 % K8) << 3;
    const float4 u0 = *(const float4*)(h + (size_t)r * H3 + k);
    const float4 u1 = *(const float4*)(h + (size_t)r * H3 + k + 4);
    const float a[8] = {u0.x, u0.y, u0.z, u0.w, u1.x, u1.y, u1.z, u1.w};
    __nv_bfloat16 hh[8], ll[8];
    #pragma unroll
    for (int q = 0; q < 8; q++) {
        const int col = k + q;
        const double mu = g_sum[col] / (double)NNODE;
        const double var = g_sq[col] / (double)NNODE - mu * mu;
        const float rstd = rsqrtf((float)var + BN_EPS);
        float v = (a[q] - (float)mu) * rstd * gamma[col] + beta[col];
        v = v > 0.0f ? v : 0.0f;
        hh[q] = __float2bfloat16(v);
        ll[q] = __float2bfloat16(v - __bfloat162float(hh[q]));
    }
    const size_t o = pcs_off(r, k, H3);
    __nv_bfloat162* ph = (__nv_bfloat162*)((char*)oh + o);
    __nv_bfloat162* pl = (__nv_bfloat162*)((char*)ol + o);
    #pragma unroll
    for (int q = 0; q < 4; q++) {
        ph[q] = __halves2bfloat162(hh[2 * q], hh[2 * q + 1]);
        pl[q] = __halves2bfloat162(ll[2 * q], ll[2 * q + 1]);
    }
}

// ---------------------------------------------------------------------------
// Orchestration
// ---------------------------------------------------------------------------
extern "C" void kernel_launch(void* const* d_in, const int* in_sizes, int n_in,
                              void* d_out, int out_size)
{
    const float* x     = (const float*)d_in[0];
    const float* adj   = (const float*)d_in[1];
    const float* W1    = (const float*)d_in[2];
    const float* b1    = (const float*)d_in[3];
    const float* W2    = (const float*)d_in[4];
    const float* b2    = (const float*)d_in[5];
    const float* gamma = (const float*)d_in[6];
    const float* beta  = (const float*)d_in[7];
    const float* Wf    = (const float*)d_in[8];
    const float* bf    = (const float*)d_in[9];
    float* out = (float*)d_out;

    __nv_bfloat16 *adj_h, *adj_l, *x_h, *x_l, *W1t_h, *W1t_l, *W2t_h, *W2t_l;
    __nv_bfloat16 *Wft_h, *Wft_l, *T12t_h, *T12t_l, *T3t_h, *T3t_l;
    __nv_bfloat16 *U12t_h, *U12t_l, *U3t_h, *U3t_l, *h1_h, *h1_l, *h2_h, *h2_l;
    float *h1;
    cudaGetSymbolAddress((void**)&adj_h, g_adj_h);
    cudaGetSymbolAddress((void**)&adj_l, g_adj_l);
    cudaGetSymbolAddress((void**)&x_h, g_x_h);
    cudaGetSymbolAddress((void**)&x_l, g_x_l);
    cudaGetSymbolAddress((void**)&W1t_h, g_W1t_h);
    cudaGetSymbolAddress((void**)&W1t_l, g_W1t_l);
    cudaGetSymbolAddress((void**)&W2t_h, g_W2t_h);
    cudaGetSymbolAddress((void**)&W2t_l, g_W2t_l);
    cudaGetSymbolAddress((void**)&Wft_h, g_Wft_h);
    cudaGetSymbolAddress((void**)&Wft_l, g_Wft_l);
    cudaGetSymbolAddress((void**)&T12t_h, g_T12t_h);
    cudaGetSymbolAddress((void**)&T12t_l, g_T12t_l);
    cudaGetSymbolAddress((void**)&T3t_h, g_T3t_h);
    cudaGetSymbolAddress((void**)&T3t_l, g_T3t_l);
    cudaGetSymbolAddress((void**)&U12t_h, g_U12t_h);
    cudaGetSymbolAddress((void**)&U12t_l, g_U12t_l);
    cudaGetSymbolAddress((void**)&U3t_h, g_U3t_h);
    cudaGetSymbolAddress((void**)&U3t_l, g_U3t_l);
    cudaGetSymbolAddress((void**)&h1_h, g_h1_h);
    cudaGetSymbolAddress((void**)&h1_l, g_h1_l);
    cudaGetSymbolAddress((void**)&h2_h, g_h2_h);
    cudaGetSymbolAddress((void**)&h2_l, g_h2_l);
    cudaGetSymbolAddress((void**)&h1, g_h1);

    constexpr int SMEM256 = 1024 + 4 * ((2 + 4) * 8192);  // 197632
    constexpr int SMEM128 = 1024 + 4 * ((2 + 2) * 8192);  // 132096
    cudaFuncSetAttribute(gemm_mma<256>, cudaFuncAttributeMaxDynamicSharedMemorySize, SMEM256);
    cudaFuncSetAttribute(gemm_mma<128>, cudaFuncAttributeMaxDynamicSharedMemorySize, SMEM128);

    const int NOSPLIT = 1 << 30;
    const dim3 blk(256);
    const int MB = NNODE / 128;   // 64

    // ---- input conversions (all into PCS) ----
    {
        const size_t n8x = (size_t)NNODE * IN_DIM / 8;
        cvt_split_pcs<<<(unsigned)((n8x + 255) / 256), 256>>>(x, x_h, x_l, NNODE, IN_DIM);
        const size_t n8a = (size_t)NNODE * NNODE / 8;
        cvt_split_pcs<<<(unsigned)((n8a + 255) / 256), 256>>>(adj, adj_h, adj_l, NNODE, NNODE);
    }
    for (int j = 0; j < 3; j++) {
        cvt_split_tr_pcs<<<dim3(HID / 32, IN_DIM / 32), dim3(32, 8)>>>(
            W1 + (size_t)j * IN_DIM * HID, W1t_h + (size_t)j * HID * IN_DIM,
            W1t_l + (size_t)j * HID * IN_DIM, IN_DIM, HID);
        cvt_split_tr_pcs<<<dim3(OUTD / 32, H3 / 32), dim3(32, 8)>>>(
            W2 + (size_t)j * H3 * OUTD, W2t_h + (size_t)j * OUTD * H3,
            W2t_l + (size_t)j * OUTD * H3, H3, OUTD);
    }
    cvt_split_tr_pcs<<<dim3(OUTD / 32, O3 / 32), dim3(32, 8)>>>(Wf, Wft_h, Wft_l, O3, OUTD);

    // ---- GEMM 1: x @ [W1_0|W1_1|W1_2]  (N=1536; <512 -> h1 fp32, >=512 -> T12^T) ----
    gemm_mma<256><<<dim3(6, MB), blk, SMEM256>>>(x_h, x_l, W1t_h, W1t_l, IN_DIM,
        h1, nullptr, nullptr, H3, 0, T12t_h, T12t_l, 512, b1);

    // ---- GEMM 2: adj @ [T1|T2]  (N=1024; <512 -> h1 hop1 fp32, >=512 -> T3^T) ----
    gemm_mma<256><<<dim3(4, MB), blk, SMEM256>>>(adj_h, adj_l, T12t_h, T12t_l, NNODE,
        h1 + HID, nullptr, nullptr, H3, 0, T3t_h, T3t_l, 512, nullptr);

    // ---- GEMM 3: adj @ T3  (N=512 -> h1 hop2 fp32) ----
    gemm_mma<256><<<dim3(2, MB), blk, SMEM256>>>(adj_h, adj_l, T3t_h, T3t_l, NNODE,
        h1 + 2 * HID, nullptr, nullptr, H3, 0, nullptr, nullptr, NOSPLIT, nullptr);

    // ---- BN + ReLU -> h1 PCS bf16 ----
    zero_stats<<<(H3 + 255) / 256, 256>>>();
    bn_stats<<<dim3(H3 / 256, NNODE / 256), 256>>>(h1);
    {
        const size_t n8 = (size_t)NNODE * H3 / 8;
        bn_apply_pcs<<<(unsigned)((n8 + 255) / 256), 256>>>(h1, gamma, beta, h1_h, h1_l);
    }

    // ---- GEMM 4: h1 @ [W2_0|W2_1|W2_2]  (N=768; <256 -> h2 PCS cols 0-255, >=256 -> U12^T) ----
    gemm_mma<256><<<dim3(3, MB), blk, SMEM256>>>(h1_h, h1_l, W2t_h, W2t_l, H3,
        nullptr, h2_h, h2_l, O3, 0, U12t_h, U12t_l, 256, b2);

    // ---- GEMM 5: adj @ [U1|U2]  (N=512; <256 -> h2 PCS cols 256-511, >=256 -> U3^T) ----
    gemm_mma<256><<<dim3(2, MB), blk, SMEM256>>>(adj_h, adj_l, U12t_h, U12t_l, NNODE,
        nullptr, h2_h, h2_l, O3, OUTD, U3t_h, U3t_l, 256, nullptr);

    // ---- GEMM 6: adj @ U3  (N=256 -> h2 PCS cols 512-767) ----
    gemm_mma<128><<<dim3(2, MB), blk, SMEM128>>>(adj_h, adj_l, U3t_h, U3t_l, NNODE,
        nullptr, h2_h, h2_l, O3, 2 * OUTD, nullptr, nullptr, NOSPLIT, nullptr);

    // ---- GEMM 7: out = h2 @ Wf + bf  (N=256, fp32) ----
    gemm_mma<128><<<dim3(2, MB), blk, SMEM128>>>(h2_h, h2_l, Wft_h, Wft_l, O3,
        out, nullptr, nullptr, OUTD, 0, nullptr, nullptr, NOSPLIT, bf);
}

// round 12
// speedup vs baseline: 1.0777x; 1.0179x over previous
#include <cuda_runtime.h>
#include <cuda_bf16.h>
#include <cstdint>
#include <cstddef>

#define NNODE 8192
#define IN_DIM 128
#define HID 512
#define OUTD 256
#define H3 1536
#define O3 768
#define BN_EPS 1e-5f

// ---------------------------------------------------------------------------
// Device scratch (allocation-free). All GEMM operands live in PCS layout:
//   [R,K] bf16 -> 8KB blocks: block(p = r>>7, c = k>>5) at ((p*(K/32)+c)<<13),
//   within-block: sw_off(r&127, (k&31)>>3) + (k&7)*2  (XOR-swizzled 128x32)
// ---------------------------------------------------------------------------
__device__ __align__(1024) __nv_bfloat16 g_adj_h[(size_t)NNODE * NNODE];
__device__ __align__(1024) __nv_bfloat16 g_adj_l[(size_t)NNODE * NNODE];
__device__ __align__(1024) __nv_bfloat16 g_x_h[(size_t)NNODE * IN_DIM];
__device__ __align__(1024) __nv_bfloat16 g_x_l[(size_t)NNODE * IN_DIM];
__device__ __align__(1024) __nv_bfloat16 g_W1t_h[3 * HID * IN_DIM];      // [1536,128]
__device__ __align__(1024) __nv_bfloat16 g_W1t_l[3 * HID * IN_DIM];
__device__ __align__(1024) __nv_bfloat16 g_W2t_h[3 * OUTD * H3];         // [768,1536]
__device__ __align__(1024) __nv_bfloat16 g_W2t_l[3 * OUTD * H3];
__device__ __align__(1024) __nv_bfloat16 g_Wft_h[OUTD * O3];             // [256,768]
__device__ __align__(1024) __nv_bfloat16 g_Wft_l[OUTD * O3];
__device__ __align__(1024) __nv_bfloat16 g_T12t_h[(size_t)2 * HID * NNODE]; // [1024,8192]
__device__ __align__(1024) __nv_bfloat16 g_T12t_l[(size_t)2 * HID * NNODE];
__device__ __align__(1024) __nv_bfloat16 g_T3t_h[(size_t)HID * NNODE];      // [512,8192]
__device__ __align__(1024) __nv_bfloat16 g_T3t_l[(size_t)HID * NNODE];
__device__ __align__(1024) __nv_bfloat16 g_U12t_h[(size_t)HID * NNODE];     // [512,8192]
__device__ __align__(1024) __nv_bfloat16 g_U12t_l[(size_t)HID * NNODE];
__device__ __align__(1024) __nv_bfloat16 g_U3t_h[(size_t)OUTD * NNODE];     // [256,8192]
__device__ __align__(1024) __nv_bfloat16 g_U3t_l[(size_t)OUTD * NNODE];
__device__ float g_h1[(size_t)NNODE * H3];                                  // row-major fp32
__device__ __align__(1024) __nv_bfloat16 g_h1_h[(size_t)NNODE * H3];        // PCS [8192,1536]
__device__ __align__(1024) __nv_bfloat16 g_h1_l[(size_t)NNODE * H3];
__device__ __align__(1024) __nv_bfloat16 g_h2_h[(size_t)NNODE * O3];        // PCS [8192,768]
__device__ __align__(1024) __nv_bfloat16 g_h2_l[(size_t)NNODE * O3];
__device__ double g_sum[H3];
__device__ double g_sq[H3];

// ---------------------------------------------------------------------------
// PTX helpers (all sm_90-baseline: compile at compute_100)
// ---------------------------------------------------------------------------
__device__ __forceinline__ uint32_t smem_u32(const void* p) {
    uint32_t a;
    asm("{ .reg .u64 t; cvta.to.shared.u64 t, %1; cvt.u32.u64 %0, t; }"
        : "=r"(a) : "l"(p));
    return a;
}

__device__ __forceinline__ void ldm_x4(uint32_t* r, uint32_t a) {
    asm volatile("ldmatrix.sync.aligned.m8n8.x4.shared.b16 {%0,%1,%2,%3}, [%4];"
        : "=r"(r[0]), "=r"(r[1]), "=r"(r[2]), "=r"(r[3]) : "r"(a));
}

__device__ __forceinline__ void mma_bf16(float* c, const uint32_t* a, const uint32_t* b) {
    asm volatile(
        "mma.sync.aligned.m16n8k16.row.col.f32.bf16.bf16.f32 "
        "{%0,%1,%2,%3}, {%4,%5,%6,%7}, {%8,%9}, {%0,%1,%2,%3};"
        : "+f"(c[0]), "+f"(c[1]), "+f"(c[2]), "+f"(c[3])
        : "r"(a[0]), "r"(a[1]), "r"(a[2]), "r"(a[3]), "r"(b[0]), "r"(b[1]));
}

// swizzled offset within an 8KB 128x32 bf16 block; c = 16B-chunk index 0..3
__device__ __forceinline__ uint32_t sw_off(int r, int c) {
    return (uint32_t)(r * 64 + ((c ^ ((r >> 1) & 3)) << 4));
}

// byte offset of element (r,k) in a PCS bf16 matrix with K columns
__device__ __forceinline__ size_t pcs_off(int r, int k, int K) {
    const size_t blk = ((size_t)(r >> 7) * (size_t)(K >> 5) + (size_t)(k >> 5)) << 13;
    return blk + sw_off(r & 127, (k & 31) >> 3) + (size_t)((k & 7) * 2);
}

#define MBAR_INIT(a, n) \
    asm volatile("mbarrier.init.shared.b64 [%0], %1;" :: "r"(a), "r"((uint32_t)(n)) : "memory")
#define MBAR_EXPECT(a, n) \
    asm volatile("mbarrier.arrive.expect_tx.shared.b64 _, [%0], %1;" \
                 :: "r"(a), "r"((uint32_t)(n)) : "memory")

#define MBAR_WAIT(a, ph) do {                                                     \
    uint32_t _m = (a); uint32_t _p = (uint32_t)(ph); uint32_t _d;                 \
    asm volatile(                                                                 \
        "{\n\t.reg .pred p;\n\t"                                                  \
        "mbarrier.try_wait.parity.acquire.cta.shared::cta.b64 p, [%1], %2;\n\t"   \
        "selp.b32 %0, 1, 0, p;\n\t}"                                              \
        : "=r"(_d) : "r"(_m), "r"(_p) : "memory");                                \
    if (!_d) {                                                                    \
        asm volatile(                                                             \
            "{\n\t.reg .pred P1;\n\t"                                             \
            "WL_%=:\n\t"                                                          \
            "mbarrier.try_wait.parity.acquire.cta.shared::cta.b64 P1, [%0], %1, 0x989680;\n\t" \
            "@P1 bra.uni WD_%=;\n\t"                                              \
            "bra.uni WL_%=;\n\t"                                                  \
            "WD_%=:\n\t}"                                                         \
            :: "r"(_m), "r"(_p) : "memory");                                      \
    }                                                                             \
} while (0)

// 8KB bulk copy global -> shared with mbarrier transaction tracking
__device__ __forceinline__ void bulk_g2s(uint32_t dst, const void* src, uint32_t mbar) {
    asm volatile(
        "cp.async.bulk.shared::cluster.global.mbarrier::complete_tx::bytes [%0], [%1], %2, [%3];"
        :: "r"(dst), "l"(src), "r"(8192u), "r"(mbar) : "memory");
}

// ---------------------------------------------------------------------------
// Split-precision bf16 GEMM via mma.sync, bulk-copy loader:
//   C[M,N] = A[M,K] @ B^T    (A: PCS [M,K]; B: PCS [N,K])
//   D += Ah*Bh + Ah*Bl + Al*Bh  (fp32 accum; per-acc order hh,hl,lh preserved)
// CTA tile 128xBNx32, 256 threads (8 warps, 2x4), warp tile 64x(BN/4).
// 4-stage ring; chunks processed in PAIRS (KC % 4 == 0 for all call sites):
// wait both stage barriers, compute pair, ONE __syncthreads, refill pair.
// Epilogue (global col gc):
//   gc < splitcol:  Cf != null -> fp32 row-major C (+bias)
//                   else       -> PCS bf16 hi/lo (Ch, Cl), K=ldc, col gc+colofs
//   gc >= splitcol: transposed PCS bf16 hi/lo T at (gc-splitcol, row), K=NNODE
// ---------------------------------------------------------------------------
template <int BN>
__global__ void __launch_bounds__(256, 1)
gemm_mma(const __nv_bfloat16* __restrict__ Ah, const __nv_bfloat16* __restrict__ Al,
         const __nv_bfloat16* __restrict__ Bh, const __nv_bfloat16* __restrict__ Bl,
         int K,
         float* __restrict__ Cf,
         __nv_bfloat16* __restrict__ Ch, __nv_bfloat16* __restrict__ Cl,
         int ldc, int colofs,
         __nv_bfloat16* __restrict__ Th, __nv_bfloat16* __restrict__ Tl,
         int splitcol, const float* __restrict__ bias)
{
    constexpr int WN = BN / 4;            // warp tile cols
    constexpr int NT = WN / 8;
    constexpr int NP = WN / 16;
    constexpr int NPAN = BN / 128;        // B panels per CTA tile
    constexpr int AS = 8192;              // A half-tile bytes
    constexpr int OBH = 2 * AS;
    constexpr int OBL = 2 * AS + NPAN * 8192;
    constexpr int STG = (2 + 2 * NPAN) * 8192;
    extern __shared__ char smem[];
    const uint32_t sb = smem_u32(smem);
    const uint32_t db = sb + 1024;

    const int tid = threadIdx.x;
    const int bx = blockIdx.x, by = blockIdx.y;
    const int KC = K >> 5;                // multiple of 4 for all call sites

    if (tid == 0) {
        #pragma unroll
        for (int b = 0; b < 4; b++) MBAR_INIT(sb + 8 * b, 1);
    }
    __syncthreads();

    auto issue = [&](int c) {
        const int b = c & 3;
        const uint32_t mb = sb + 8 * b;
        const uint32_t dst = db + (uint32_t)b * STG;
        MBAR_EXPECT(mb, STG);
        bulk_g2s(dst,      (const char*)Ah + (((size_t)by * KC + c) << 13), mb);
        bulk_g2s(dst + AS, (const char*)Al + (((size_t)by * KC + c) << 13), mb);
        #pragma unroll
        for (int p = 0; p < NPAN; p++) {
            const size_t bo = ((size_t)(bx * NPAN + p) * KC + c) << 13;
            bulk_g2s(dst + OBH + p * 8192, (const char*)Bh + bo, mb);
            bulk_g2s(dst + OBL + p * 8192, (const char*)Bl + bo, mb);
        }
    };

    if (tid == 0) {
        issue(0); issue(1); issue(2); issue(3);
    }

    // ---- compute mapping: 8 warps, 2 rows x 4 cols ----
    const int w = tid >> 5, l = tid & 31;
    const int RM = (w >> 2) * 64;
    const int CN = (w & 3) * WN;

    uint32_t aoff[4][2];
    #pragma unroll
    for (int mt = 0; mt < 4; mt++) {
        const int r = RM + mt * 16 + (l & 15);
        #pragma unroll
        for (int ks = 0; ks < 2; ks++)
            aoff[mt][ks] = sw_off(r, ks * 2 + (l >> 4));
    }
    uint32_t boff[NP][2];
    #pragma unroll
    for (int np = 0; np < NP; np++) {
        const int r = CN + np * 16 + ((l >> 4) << 3) + (l & 7);
        #pragma unroll
        for (int ks = 0; ks < 2; ks++)
            boff[np][ks] = sw_off(r, ks * 2 + ((l >> 3) & 1));
    }

    float acc[4][NT][4];
    #pragma unroll
    for (int mt = 0; mt < 4; mt++)
        #pragma unroll
        for (int nt = 0; nt < NT; nt++)
            #pragma unroll
            for (int k = 0; k < 4; k++) acc[mt][nt][k] = 0.0f;

    for (int c = 0; c < KC; c += 2) {
        const uint32_t ph = (uint32_t)((c >> 2) & 1);
        MBAR_WAIT(sb + 8 * (c & 3), ph);
        MBAR_WAIT(sb + 8 * ((c + 1) & 3), ph);

        #pragma unroll
        for (int q = 0; q < 2; q++) {
            const uint32_t sbase = db + (uint32_t)((c + q) & 3) * STG;
            #pragma unroll
            for (int ks = 0; ks < 2; ks++) {
                uint32_t ahf[4][4], alf[4][4], bhf[NP][4], blf[NP][4];
                #pragma unroll
                for (int mt = 0; mt < 4; mt++) {
                    ldm_x4(ahf[mt], sbase + aoff[mt][ks]);
                    ldm_x4(alf[mt], sbase + AS + aoff[mt][ks]);
                }
                #pragma unroll
                for (int np = 0; np < NP; np++) {
                    ldm_x4(bhf[np], sbase + OBH + boff[np][ks]);
                    ldm_x4(blf[np], sbase + OBL + boff[np][ks]);
                }
                // Product-major ordering: each acc touched once per sweep
                // (per-acc order hh -> hl -> lh preserved = identical numerics)
                #pragma unroll
                for (int np = 0; np < NP; np++)
                    #pragma unroll
                    for (int mt = 0; mt < 4; mt++)
                        #pragma unroll
                        for (int s = 0; s < 2; s++)
                            mma_bf16(acc[mt][2 * np + s], ahf[mt], &bhf[np][s * 2]);
                #pragma unroll
                for (int np = 0; np < NP; np++)
                    #pragma unroll
                    for (int mt = 0; mt < 4; mt++)
                        #pragma unroll
                        for (int s = 0; s < 2; s++)
                            mma_bf16(acc[mt][2 * np + s], ahf[mt], &blf[np][s * 2]);
                #pragma unroll
                for (int np = 0; np < NP; np++)
                    #pragma unroll
                    for (int mt = 0; mt < 4; mt++)
                        #pragma unroll
                        for (int s = 0; s < 2; s++)
                            mma_bf16(acc[mt][2 * np + s], alf[mt], &bhf[np][s * 2]);
            }
        }
        __syncthreads();
        if (tid == 0) {
            if (c + 4 < KC) issue(c + 4);
            if (c + 5 < KC) issue(c + 5);
        }
    }

    // ---- epilogue ----
    #pragma unroll
    for (int mt = 0; mt < 4; mt++) {
        const int r0 = by * 128 + RM + mt * 16 + (l >> 2);
        #pragma unroll
        for (int nt = 0; nt < NT; nt++) {
            const int gc = bx * BN + CN + nt * 8 + ((l & 3) << 1);
            float v0 = acc[mt][nt][0], v1 = acc[mt][nt][1];
            float v2 = acc[mt][nt][2], v3 = acc[mt][nt][3];
            if (bias) {
                const float bb0 = __ldg(bias + gc), bb1 = __ldg(bias + gc + 1);
                v0 += bb0; v1 += bb1; v2 += bb0; v3 += bb1;
            }
            if (gc < splitcol) {
                if (Cf) {
                    *(float2*)&Cf[(size_t)r0 * ldc + gc] = make_float2(v0, v1);
                    *(float2*)&Cf[(size_t)(r0 + 8) * ldc + gc] = make_float2(v2, v3);
                } else {
                    const int pc = gc + colofs;
                    const __nv_bfloat16 h0 = __float2bfloat16(v0);
                    const __nv_bfloat16 h1 = __float2bfloat16(v1);
                    const __nv_bfloat16 h2 = __float2bfloat16(v2);
                    const __nv_bfloat16 h3 = __float2bfloat16(v3);
                    const size_t oA = pcs_off(r0, pc, ldc);
                    const size_t oB = pcs_off(r0 + 8, pc, ldc);
                    *(__nv_bfloat162*)((char*)Ch + oA) = __halves2bfloat162(h0, h1);
                    *(__nv_bfloat162*)((char*)Ch + oB) = __halves2bfloat162(h2, h3);
                    *(__nv_bfloat162*)((char*)Cl + oA) = __halves2bfloat162(
                        __float2bfloat16(v0 - __bfloat162float(h0)),
                        __float2bfloat16(v1 - __bfloat162float(h1)));
                    *(__nv_bfloat162*)((char*)Cl + oB) = __halves2bfloat162(
                        __float2bfloat16(v2 - __bfloat162float(h2)),
                        __float2bfloat16(v3 - __bfloat162float(h3)));
                }
            } else {
                const int tr = gc - splitcol;
                const float vv[4] = {v0, v1, v2, v3};
                const size_t oo[4] = {
                    pcs_off(tr, r0, NNODE), pcs_off(tr + 1, r0, NNODE),
                    pcs_off(tr, r0 + 8, NNODE), pcs_off(tr + 1, r0 + 8, NNODE)};
                #pragma unroll
                for (int q = 0; q < 4; q++) {
                    const __nv_bfloat16 h = __float2bfloat16(vv[q]);
                    *(__nv_bfloat16*)((char*)Th + oo[q]) = h;
                    *(__nv_bfloat16*)((char*)Tl + oo[q]) =
                        __float2bfloat16(vv[q] - __bfloat162float(h));
                }
            }
        }
    }
}

// ---------------------------------------------------------------------------
// fp32 row-major [R,K] -> PCS bf16 hi/lo
// ---------------------------------------------------------------------------
__global__ void cvt_split_pcs(const float* __restrict__ s,
                              __nv_bfloat16* __restrict__ dh,
                              __nv_bfloat16* __restrict__ dl, int R, int K)
{
    const int K8 = K >> 3;
    const size_t i8 = (size_t)blockIdx.x * 256 + threadIdx.x;
    if (i8 >= (size_t)R * K8) return;
    const int r = (int)(i8 / K8);
    const int k = (int)(i8 % K8) << 3;
    const float4 u0 = *(const float4*)(s + (size_t)r * K + k);
    const float4 u1 = *(const float4*)(s + (size_t)r * K + k + 4);
    const float a[8] = {u0.x, u0.y, u0.z, u0.w, u1.x, u1.y, u1.z, u1.w};
    __nv_bfloat16 hh[8], ll[8];
    #pragma unroll
    for (int q = 0; q < 8; q++) {
        hh[q] = __float2bfloat16(a[q]);
        ll[q] = __float2bfloat16(a[q] - __bfloat162float(hh[q]));
    }
    const size_t o = pcs_off(r, k, K);
    __nv_bfloat162* ph = (__nv_bfloat162*)((char*)dh + o);
    __nv_bfloat162* pl = (__nv_bfloat162*)((char*)dl + o);
    #pragma unroll
    for (int q = 0; q < 4; q++) {
        ph[q] = __halves2bfloat162(hh[2 * q], hh[2 * q + 1]);
        pl[q] = __halves2bfloat162(ll[2 * q], ll[2 * q + 1]);
    }
}

// fp32 [R,C] row-major -> transposed PCS bf16 hi/lo [C rows, R cols].
// blockIdx.z selects a weight slice: src + z*inStride, dst + z*outStride.
__global__ void cvt_split_tr_pcs(const float* __restrict__ s,
                                 __nv_bfloat16* __restrict__ dh,
                                 __nv_bfloat16* __restrict__ dl, int R, int C,
                                 size_t inStride, size_t outStride)
{
    __shared__ float t[32][33];
    const float* src = s + (size_t)blockIdx.z * inStride;
    __nv_bfloat16* odh = dh + (size_t)blockIdx.z * outStride;
    __nv_bfloat16* odl = dl + (size_t)blockIdx.z * outStride;
    const int c0 = blockIdx.x * 32, r0 = blockIdx.y * 32;
    const int tx = threadIdx.x, ty = threadIdx.y;
    #pragma unroll
    for (int j = 0; j < 4; j++)
        t[ty + 8 * j][tx] = src[(size_t)(r0 + ty + 8 * j) * C + c0 + tx];
    __syncthreads();
    #pragma unroll
    for (int j = 0; j < 4; j++) {
        const float v = t[tx][ty + 8 * j];
        const __nv_bfloat16 h = __float2bfloat16(v);
        const __nv_bfloat16 l = __float2bfloat16(v - __bfloat162float(h));
        const size_t o = pcs_off(c0 + ty + 8 * j, r0 + tx, R);
        *(__nv_bfloat16*)((char*)odh + o) = h;
        *(__nv_bfloat16*)((char*)odl + o) = l;
    }
}

// ---------------------------------------------------------------------------
// BatchNorm (training stats) + ReLU; fp32 h1 -> PCS bf16 hi/lo
// ---------------------------------------------------------------------------
__global__ void zero_stats()
{
    const int i = blockIdx.x * blockDim.x + threadIdx.x;
    if (i < H3) { g_sum[i] = 0.0; g_sq[i] = 0.0; }
}

__global__ void bn_stats(const float* __restrict__ h)
{
    const int col = blockIdx.x * 256 + threadIdx.x;
    const int r0 = blockIdx.y * 256;
    double ls = 0.0, lq = 0.0;
    #pragma unroll 4
    for (int r = r0; r < r0 + 256; r++) {
        const float v = h[(size_t)r * H3 + col];
        ls += (double)v;
        lq += (double)v * (double)v;
    }
    atomicAdd(&g_sum[col], ls);
    atomicAdd(&g_sq[col], lq);
}

__global__ void bn_apply_pcs(const float* __restrict__ h,
                             const float* __restrict__ gamma,
                             const float* __restrict__ beta,
                             __nv_bfloat16* __restrict__ oh,
                             __nv_bfloat16* __restrict__ ol)
{
    constexpr int K8 = H3 >> 3;
    const size_t i8 = (size_t)blockIdx.x * 256 + threadIdx.x;
    if (i8 >= (size_t)NNODE * K8) return;
    const int r = (int)(i8 / K8);
    const int k = (int)(i8 % K8) << 3;
    const float4 u0 = *(const float4*)(h + (size_t)r * H3 + k);
    const float4 u1 = *(const float4*)(h + (size_t)r * H3 + k + 4);
    const float a[8] = {u0.x, u0.y, u0.z, u0.w, u1.x, u1.y, u1.z, u1.w};
    __nv_bfloat16 hh[8], ll[8];
    #pragma unroll
    for (int q = 0; q < 8; q++) {
        const int col = k + q;
        const double mu = g_sum[col] / (double)NNODE;
        const double var = g_sq[col] / (double)NNODE - mu * mu;
        const float rstd = rsqrtf((float)var + BN_EPS);
        float v = (a[q] - (float)mu) * rstd * gamma[col] + beta[col];
        v = v > 0.0f ? v : 0.0f;
        hh[q] = __float2bfloat16(v);
        ll[q] = __float2bfloat16(v - __bfloat162float(hh[q]));
    }
    const size_t o = pcs_off(r, k, H3);
    __nv_bfloat162* ph = (__nv_bfloat162*)((char*)oh + o);
    __nv_bfloat162* pl = (__nv_bfloat162*)((char*)ol + o);
    #pragma unroll
    for (int q = 0; q < 4; q++) {
        ph[q] = __halves2bfloat162(hh[2 * q], hh[2 * q + 1]);
        pl[q] = __halves2bfloat162(ll[2 * q], ll[2 * q + 1]);
    }
}

// ---------------------------------------------------------------------------
// Orchestration
// ---------------------------------------------------------------------------
extern "C" void kernel_launch(void* const* d_in, const int* in_sizes, int n_in,
                              void* d_out, int out_size)
{
    const float* x     = (const float*)d_in[0];
    const float* adj   = (const float*)d_in[1];
    const float* W1    = (const float*)d_in[2];
    const float* b1    = (const float*)d_in[3];
    const float* W2    = (const float*)d_in[4];
    const float* b2    = (const float*)d_in[5];
    const float* gamma = (const float*)d_in[6];
    const float* beta  = (const float*)d_in[7];
    const float* Wf    = (const float*)d_in[8];
    const float* bf    = (const float*)d_in[9];
    float* out = (float*)d_out;

    __nv_bfloat16 *adj_h, *adj_l, *x_h, *x_l, *W1t_h, *W1t_l, *W2t_h, *W2t_l;
    __nv_bfloat16 *Wft_h, *Wft_l, *T12t_h, *T12t_l, *T3t_h, *T3t_l;
    __nv_bfloat16 *U12t_h, *U12t_l, *U3t_h, *U3t_l, *h1_h, *h1_l, *h2_h, *h2_l;
    float *h1;
    cudaGetSymbolAddress((void**)&adj_h, g_adj_h);
    cudaGetSymbolAddress((void**)&adj_l, g_adj_l);
    cudaGetSymbolAddress((void**)&x_h, g_x_h);
    cudaGetSymbolAddress((void**)&x_l, g_x_l);
    cudaGetSymbolAddress((void**)&W1t_h, g_W1t_h);
    cudaGetSymbolAddress((void**)&W1t_l, g_W1t_l);
    cudaGetSymbolAddress((void**)&W2t_h, g_W2t_h);
    cudaGetSymbolAddress((void**)&W2t_l, g_W2t_l);
    cudaGetSymbolAddress((void**)&Wft_h, g_Wft_h);
    cudaGetSymbolAddress((void**)&Wft_l, g_Wft_l);
    cudaGetSymbolAddress((void**)&T12t_h, g_T12t_h);
    cudaGetSymbolAddress((void**)&T12t_l, g_T12t_l);
    cudaGetSymbolAddress((void**)&T3t_h, g_T3t_h);
    cudaGetSymbolAddress((void**)&T3t_l, g_T3t_l);
    cudaGetSymbolAddress((void**)&U12t_h, g_U12t_h);
    cudaGetSymbolAddress((void**)&U12t_l, g_U12t_l);
    cudaGetSymbolAddress((void**)&U3t_h, g_U3t_h);
    cudaGetSymbolAddress((void**)&U3t_l, g_U3t_l);
    cudaGetSymbolAddress((void**)&h1_h, g_h1_h);
    cudaGetSymbolAddress((void**)&h1_l, g_h1_l);
    cudaGetSymbolAddress((void**)&h2_h, g_h2_h);
    cudaGetSymbolAddress((void**)&h2_l, g_h2_l);
    cudaGetSymbolAddress((void**)&h1, g_h1);

    constexpr int SMEM256 = 1024 + 4 * ((2 + 4) * 8192);  // 197632
    constexpr int SMEM128 = 1024 + 4 * ((2 + 2) * 8192);  // 132096
    cudaFuncSetAttribute(gemm_mma<256>, cudaFuncAttributeMaxDynamicSharedMemorySize, SMEM256);
    cudaFuncSetAttribute(gemm_mma<128>, cudaFuncAttributeMaxDynamicSharedMemorySize, SMEM128);

    const int NOSPLIT = 1 << 30;
    const dim3 blk(256);
    const int MB = NNODE / 128;   // 64

    // ---- input conversions (all into PCS) ----
    {
        const size_t n8x = (size_t)NNODE * IN_DIM / 8;
        cvt_split_pcs<<<(unsigned)((n8x + 255) / 256), 256>>>(x, x_h, x_l, NNODE, IN_DIM);
        const size_t n8a = (size_t)NNODE * NNODE / 8;
        cvt_split_pcs<<<(unsigned)((n8a + 255) / 256), 256>>>(adj, adj_h, adj_l, NNODE, NNODE);
    }
    // W1: 3 slices batched via grid.z; W2: 3 slices; Wf: 1 slice
    cvt_split_tr_pcs<<<dim3(HID / 32, IN_DIM / 32, 3), dim3(32, 8)>>>(
        W1, W1t_h, W1t_l, IN_DIM, HID,
        (size_t)IN_DIM * HID, (size_t)HID * IN_DIM);
    cvt_split_tr_pcs<<<dim3(OUTD / 32, H3 / 32, 3), dim3(32, 8)>>>(
        W2, W2t_h, W2t_l, H3, OUTD,
        (size_t)H3 * OUTD, (size_t)OUTD * H3);
    cvt_split_tr_pcs<<<dim3(OUTD / 32, O3 / 32, 1), dim3(32, 8)>>>(
        Wf, Wft_h, Wft_l, O3, OUTD, 0, 0);

    // ---- GEMM 1: x @ [W1_0|W1_1|W1_2]  (N=1536; <512 -> h1 fp32, >=512 -> T12^T) ----
    gemm_mma<256><<<dim3(6, MB), blk, SMEM256>>>(x_h, x_l, W1t_h, W1t_l, IN_DIM,
        h1, nullptr, nullptr, H3, 0, T12t_h, T12t_l, 512, b1);

    // ---- GEMM 2: adj @ [T1|T2]  (N=1024; <512 -> h1 hop1 fp32, >=512 -> T3^T) ----
    gemm_mma<256><<<dim3(4, MB), blk, SMEM256>>>(adj_h, adj_l, T12t_h, T12t_l, NNODE,
        h1 + HID, nullptr, nullptr, H3, 0, T3t_h, T3t_l, 512, nullptr);

    // ---- GEMM 3: adj @ T3  (N=512 -> h1 hop2 fp32) ----
    gemm_mma<256><<<dim3(2, MB), blk, SMEM256>>>(adj_h, adj_l, T3t_h, T3t_l, NNODE,
        h1 + 2 * HID, nullptr, nullptr, H3, 0, nullptr, nullptr, NOSPLIT, nullptr);

    // ---- BN + ReLU -> h1 PCS bf16 ----
    zero_stats<<<(H3 + 255) / 256, 256>>>();
    bn_stats<<<dim3(H3 / 256, NNODE / 256), 256>>>(h1);
    {
        const size_t n8 = (size_t)NNODE * H3 / 8;
        bn_apply_pcs<<<(unsigned)((n8 + 255) / 256), 256>>>(h1, gamma, beta, h1_h, h1_l);
    }

    // ---- GEMM 4: h1 @ [W2_0|W2_1|W2_2]  (N=768, BN=128 -> 384 CTAs for better
    //      wave packing; <256 -> h2 PCS cols 0-255, >=256 -> U12^T) ----
    gemm_mma<128><<<dim3(6, MB), blk, SMEM128>>>(h1_h, h1_l, W2t_h, W2t_l, H3,
        nullptr, h2_h, h2_l, O3, 0, U12t_h, U12t_l, 256, b2);

    // ---- GEMM 5: adj @ [U1|U2]  (N=512; <256 -> h2 PCS cols 256-511, >=256 -> U3^T) ----
    gemm_mma<256><<<dim3(2, MB), blk, SMEM256>>>(adj_h, adj_l, U12t_h, U12t_l, NNODE,
        nullptr, h2_h, h2_l, O3, OUTD, U3t_h, U3t_l, 256, nullptr);

    // ---- GEMM 6: adj @ U3  (N=256 -> h2 PCS cols 512-767) ----
    gemm_mma<128><<<dim3(2, MB), blk, SMEM128>>>(adj_h, adj_l, U3t_h, U3t_l, NNODE,
        nullptr, h2_h, h2_l, O3, 2 * OUTD, nullptr, nullptr, NOSPLIT, nullptr);

    // ---- GEMM 7: out = h2 @ Wf + bf  (N=256, fp32) ----
    gemm_mma<128><<<dim3(2, MB), blk, SMEM128>>>(h2_h, h2_l, Wft_h, Wft_l, O3,
        out, nullptr, nullptr, OUTD, 0, nullptr, nullptr, NOSPLIT, bf);
}